// round 3
// baseline (speedup 1.0000x reference)
#include <cuda_runtime.h>
#include <math.h>

#define BATCH   4
#define SEQ     2048
#define FEATS   1024
#define HEADS   16
#define HDIM    64
#define MROWS   (BATCH*SEQ)   // 8192

// Scratch (device globals: allocation-free rule)
__device__ float g_Q[MROWS*FEATS];                 // 32 MB (normalized in place)
__device__ float g_K[MROWS*FEATS];                 // 32 MB (normalized in place)
__device__ float g_V[MROWS*FEATS];                 // 32 MB
__device__ float g_T[BATCH*HEADS*HDIM*HDIM];       // 1 MB  : (K^T V)/scale per (b,h)
__device__ float g_Weff[BATCH*FEATS*FEATS];        // 16 MB : per-batch folded T*Wo

// ---------------------------------------------------------------------------
// Batched SGEMM: C[z] = A[z] @ W[z] + bias ;  A row-major [M,K], W row-major [K,N]
// BM=128 BN=128 BK=16, 256 threads, 8x8 per thread.
// ---------------------------------------------------------------------------
__global__ __launch_bounds__(256, 2) void sgemm_bias_kernel(
    const float* __restrict__ A, size_t strideA,
    const float* __restrict__ W, size_t strideW,
    const float* __restrict__ bias,
    float* __restrict__ C, size_t strideC,
    int M, int N, int K)
{
    const int BM = 128, BN = 128, BK = 16;
    __shared__ float As[BK][BM];   // transposed A tile
    __shared__ float Ws[BK][BN];

    A += (size_t)blockIdx.z * strideA;
    W += (size_t)blockIdx.z * strideW;
    C += (size_t)blockIdx.z * strideC;

    const int t  = threadIdx.x;
    const int bm = blockIdx.y * BM;
    const int bn = blockIdx.x * BN;
    const int tx = t & 15;        // 0..15 -> col group
    const int ty = t >> 4;        // 0..15 -> row group

    // A tile loader: 128 rows x 16 cols ; thread loads rows {t/4, t/4+64}, 4 cols
    const int arow = t >> 2;           // 0..63
    const int acol = (t & 3) * 4;      // 0,4,8,12
    // W tile loader: 16 rows x 128 cols ; thread loads rows {t/32, t/32+8}, 4 cols
    const int wrow = t >> 5;           // 0..7
    const int wcol = (t & 31) * 4;     // 0..124

    float acc[8][8];
#pragma unroll
    for (int i = 0; i < 8; i++)
#pragma unroll
        for (int j = 0; j < 8; j++) acc[i][j] = 0.0f;

    for (int k0 = 0; k0 < K; k0 += BK) {
#pragma unroll
        for (int i = 0; i < 2; i++) {
            int r = arow + i * 64;
            float4 v = *(const float4*)&A[(size_t)(bm + r) * K + k0 + acol];
            As[acol + 0][r] = v.x;
            As[acol + 1][r] = v.y;
            As[acol + 2][r] = v.z;
            As[acol + 3][r] = v.w;
        }
#pragma unroll
        for (int i = 0; i < 2; i++) {
            int r = wrow + i * 8;
            *(float4*)&Ws[r][wcol] = *(const float4*)&W[(size_t)(k0 + r) * N + bn + wcol];
        }
        __syncthreads();

#pragma unroll
        for (int kk = 0; kk < BK; kk++) {
            float ra[8], rb[8];
            *(float4*)&ra[0] = *(const float4*)&As[kk][ty * 8];
            *(float4*)&ra[4] = *(const float4*)&As[kk][ty * 8 + 4];
            *(float4*)&rb[0] = *(const float4*)&Ws[kk][tx * 8];
            *(float4*)&rb[4] = *(const float4*)&Ws[kk][tx * 8 + 4];
#pragma unroll
            for (int i = 0; i < 8; i++)
#pragma unroll
                for (int j = 0; j < 8; j++)
                    acc[i][j] += ra[i] * rb[j];
        }
        __syncthreads();
    }

#pragma unroll
    for (int i = 0; i < 8; i++) {
        int mrow = bm + ty * 8 + i;
#pragma unroll
        for (int j = 0; j < 8; j += 4) {
            int n = bn + tx * 8 + j;
            float4 o;
            o.x = acc[i][j + 0] + bias[n + 0];
            o.y = acc[i][j + 1] + bias[n + 1];
            o.z = acc[i][j + 2] + bias[n + 2];
            o.w = acc[i][j + 3] + bias[n + 3];
            *(float4*)&C[(size_t)mrow * N + n] = o;
        }
    }
}

// ---------------------------------------------------------------------------
// L2-normalize each 64-elem head chunk of Q and K in place (F.normalize, eps=1e-12)
// One warp per group; group g of tensor p at base + g*64.
// ---------------------------------------------------------------------------
__global__ __launch_bounds__(256) void l2norm_kernel(float* __restrict__ Q,
                                                     float* __restrict__ K)
{
    const int ngroups = MROWS * HEADS;  // 131072 per tensor
    int wid  = (blockIdx.x * blockDim.x + threadIdx.x) >> 5;
    int lane = threadIdx.x & 31;
    if (wid >= 2 * ngroups) return;
    float* base = (wid < ngroups) ? Q : K;
    int g = (wid < ngroups) ? wid : wid - ngroups;
    float* p = base + (size_t)g * HDIM;

    float2 v = *(float2*)(p + lane * 2);
    float ss = v.x * v.x + v.y * v.y;
#pragma unroll
    for (int o = 16; o > 0; o >>= 1) ss += __shfl_xor_sync(0xFFFFFFFFu, ss, o);
    float nrm = sqrtf(ss);
    float inv = 1.0f / fmaxf(nrm, 1e-12f);
    v.x *= inv; v.y *= inv;
    *(float2*)(p + lane * 2) = v;
}

// ---------------------------------------------------------------------------
// T[b,h] = (K_{b,h}^T @ V_{b,h}) * SEQ^{-sigmoid(m[h])}   -> [64x64] per head
// grid = 64 (b*HEADS+h), 256 threads, each 4x4 accumulators.
// ---------------------------------------------------------------------------
__global__ __launch_bounds__(256) void ktv_kernel(const float* __restrict__ Kb,
                                                  const float* __restrict__ Vb,
                                                  const float* __restrict__ m,
                                                  float* __restrict__ T)
{
    int bh = blockIdx.x;
    int b = bh >> 4, h = bh & 15;
    __shared__ float Ks[32][64];
    __shared__ float Vs[32][64];
    const int tid = threadIdx.x;
    const int tx = tid & 15, ty = tid >> 4;
    const int lr = tid >> 4;          // 0..15 (rows lr, lr+16)
    const int lc = (tid & 15) * 4;    // 0..60

    const float* Kp = Kb + (size_t)b * SEQ * FEATS + h * HDIM;
    const float* Vp = Vb + (size_t)b * SEQ * FEATS + h * HDIM;

    float acc[4][4];
#pragma unroll
    for (int i = 0; i < 4; i++)
#pragma unroll
        for (int j = 0; j < 4; j++) acc[i][j] = 0.0f;

    for (int j0 = 0; j0 < SEQ; j0 += 32) {
#pragma unroll
        for (int i = 0; i < 2; i++) {
            int r = lr + i * 16;
            *(float4*)&Ks[r][lc] = *(const float4*)&Kp[(size_t)(j0 + r) * FEATS + lc];
            *(float4*)&Vs[r][lc] = *(const float4*)&Vp[(size_t)(j0 + r) * FEATS + lc];
        }
        __syncthreads();
#pragma unroll
        for (int j = 0; j < 32; j++) {
            float ra[4], rb[4];
            *(float4*)ra = *(const float4*)&Ks[j][ty * 4];
            *(float4*)rb = *(const float4*)&Vs[j][tx * 4];
#pragma unroll
            for (int i = 0; i < 4; i++)
#pragma unroll
                for (int c = 0; c < 4; c++)
                    acc[i][c] += ra[i] * rb[c];
        }
        __syncthreads();
    }

    float sig = 1.0f / (1.0f + expf(-m[h]));
    float invscale = powf((float)SEQ, -sig);

#pragma unroll
    for (int i = 0; i < 4; i++) {
        int e = ty * 4 + i;
        float4 o;
        o.x = acc[i][0] * invscale;
        o.y = acc[i][1] * invscale;
        o.z = acc[i][2] * invscale;
        o.w = acc[i][3] * invscale;
        *(float4*)&T[(size_t)bh * 4096 + e * 64 + tx * 4] = o;
    }
}

// ---------------------------------------------------------------------------
// Weff[b][h*64+e][n] = sum_d T[b,h][e][d] * Wo[h*64+d][n]
// grid = (16 n-chunks of 64, 64 bh), 256 threads.
// ---------------------------------------------------------------------------
__global__ __launch_bounds__(256) void weff_kernel(const float* __restrict__ T,
                                                   const float* __restrict__ Wo,
                                                   float* __restrict__ Weff)
{
    int bh = blockIdx.y;
    int b = bh >> 4, h = bh & 15;
    int n0 = blockIdx.x * 64;
    __shared__ float Tst[64][64];   // Tst[d][e] = T[e][d]
    __shared__ float Ws[64][64];    // Ws[d][nn] = Wo[h*64+d][n0+nn]
    const int tid = threadIdx.x;
    const int lr = tid >> 4;           // 0..15
    const int lc = (tid & 15) * 4;     // 0..60

#pragma unroll
    for (int i = 0; i < 4; i++) {
        int r = lr + i * 16;
        float4 v = *(const float4*)&T[(size_t)bh * 4096 + r * 64 + lc];
        Tst[lc + 0][r] = v.x;
        Tst[lc + 1][r] = v.y;
        Tst[lc + 2][r] = v.z;
        Tst[lc + 3][r] = v.w;
        *(float4*)&Ws[r][lc] = *(const float4*)&Wo[(size_t)(h * HDIM + r) * FEATS + n0 + lc];
    }
    __syncthreads();

    const int tx = tid & 15, ty = tid >> 4;
    float acc[4][4];
#pragma unroll
    for (int i = 0; i < 4; i++)
#pragma unroll
        for (int j = 0; j < 4; j++) acc[i][j] = 0.0f;

#pragma unroll
    for (int d = 0; d < 64; d++) {
        float ra[4], rb[4];
        *(float4*)ra = *(const float4*)&Tst[d][ty * 4];
        *(float4*)rb = *(const float4*)&Ws[d][tx * 4];
#pragma unroll
        for (int i = 0; i < 4; i++)
#pragma unroll
            for (int j = 0; j < 4; j++)
                acc[i][j] += ra[i] * rb[j];
    }

#pragma unroll
    for (int i = 0; i < 4; i++) {
        int e = ty * 4 + i;
        float4 o;
        o.x = acc[i][0]; o.y = acc[i][1]; o.z = acc[i][2]; o.w = acc[i][3];
        *(float4*)&Weff[((size_t)b * FEATS + h * HDIM + e) * FEATS + n0 + tx * 4] = o;
    }
}

// ---------------------------------------------------------------------------
// kernel_launch
// Inputs: x, Wq, bq, Wk, bk, Wv, bv, Wo, bo, m   (all fp32)
// Output: [4, 2048, 1024] fp32
// ---------------------------------------------------------------------------
extern "C" void kernel_launch(void* const* d_in, const int* in_sizes, int n_in,
                              void* d_out, int out_size)
{
    (void)in_sizes; (void)n_in; (void)out_size;
    const float* x  = (const float*)d_in[0];
    const float* Wq = (const float*)d_in[1];
    const float* bq = (const float*)d_in[2];
    const float* Wk = (const float*)d_in[3];
    const float* bk = (const float*)d_in[4];
    const float* Wv = (const float*)d_in[5];
    const float* bv = (const float*)d_in[6];
    const float* Wo = (const float*)d_in[7];
    const float* bo = (const float*)d_in[8];
    const float* m  = (const float*)d_in[9];
    float* out = (float*)d_out;

    float *Q, *K, *V, *T, *Weff;
    cudaGetSymbolAddress((void**)&Q,    g_Q);
    cudaGetSymbolAddress((void**)&K,    g_K);
    cudaGetSymbolAddress((void**)&V,    g_V);
    cudaGetSymbolAddress((void**)&T,    g_T);
    cudaGetSymbolAddress((void**)&Weff, g_Weff);

    dim3 blk(256);

    // 1) Q/K/V projections: [8192,1024] @ [1024,1024]
    dim3 gqkv(FEATS / 128, MROWS / 128, 1);
    sgemm_bias_kernel<<<gqkv, blk>>>(x, 0, Wq, 0, bq, Q, 0, MROWS, FEATS, FEATS);
    sgemm_bias_kernel<<<gqkv, blk>>>(x, 0, Wk, 0, bk, K, 0, MROWS, FEATS, FEATS);
    sgemm_bias_kernel<<<gqkv, blk>>>(x, 0, Wv, 0, bv, V, 0, MROWS, FEATS, FEATS);

    // 2) L2-normalize Q and K per head chunk (in place).
    // total warps = 2 * MROWS * HEADS = 262144 ; 8 warps per 256-thread block.
    {
        int total_warps = 2 * MROWS * HEADS;          // 262144
        int nblocks = total_warps / 8;                // 32768
        l2norm_kernel<<<nblocks, 256>>>(Q, K);
    }

    // 3) T = (K^T V)/scale per (b,h)
    ktv_kernel<<<BATCH * HEADS, blk>>>(K, V, m, T);

    // 4) Fold T into Wo per batch: Weff_b = blockrows(T_bh @ Wo_h)
    weff_kernel<<<dim3(FEATS / 64, BATCH * HEADS), blk>>>(T, Wo, Weff);

    // 5) out_b = Qn_b @ Weff_b + bo
    dim3 gout(FEATS / 128, SEQ / 128, BATCH);
    sgemm_bias_kernel<<<gout, blk>>>(Q, (size_t)SEQ * FEATS,
                                     Weff, (size_t)FEATS * FEATS,
                                     bo, out, (size_t)SEQ * FEATS,
                                     SEQ, FEATS, FEATS);
}

// round 5
// speedup vs baseline: 1.2328x; 1.2328x over previous
#include <cuda_runtime.h>
#include <math.h>
#include <stdint.h>

#define BATCH   4
#define SEQ     2048
#define FEATS   1024
#define HEADS   16
#define HDIM    64
#define MROWS   (BATCH*SEQ)   // 8192

// Scratch (device globals: allocation-free rule)
__device__ float g_Q[MROWS*FEATS];                 // 32 MB (normalized in place)
__device__ float g_K[MROWS*FEATS];                 // 32 MB (normalized in place)
__device__ float g_V[MROWS*FEATS];                 // 32 MB
__device__ float g_T[BATCH*HEADS*HDIM*HDIM];       // 1 MB  : (K^T V)/scale per (b,h)
__device__ float g_Weff[BATCH*FEATS*FEATS];        // 16 MB : per-batch folded T*Wo

__device__ __forceinline__ uint32_t f2tf32(float f) {
    uint32_t u;
    asm("cvt.rna.tf32.f32 %0, %1;" : "=r"(u) : "f"(f));
    return u;
}

// ---------------------------------------------------------------------------
// TF32 tensor-core GEMM: C[z] = A[z] @ W[z] + bias
// A row-major [M,K], W row-major [K,N]. BM=128 BN=128 BK=32.
// 256 threads = 8 warps (2 warp-m x 4 warp-n), warp tile 64x32, m16n8k8 mma.
// Double-buffered dynamic smem (64KB): As[2][32][128] (k-major), Bs[2][32][128].
// ---------------------------------------------------------------------------
__global__ __launch_bounds__(256) void gemm_tf32_kernel(
    const float* __restrict__ A, size_t strideA,
    const float* __restrict__ W, size_t strideW,
    const float* __restrict__ bias,
    float* __restrict__ C, size_t strideC,
    int M, int N, int K)
{
    extern __shared__ uint32_t smem_u[];
    // As at [0, 8192) words (2 stages * 32 * 128), Bs at [8192, 16384)
#define AS(st,k,mm) smem_u[(st)*4096 + (k)*128 + (mm)]
#define BS(st,k,nn) smem_u[8192 + (st)*4096 + (k)*128 + (nn)]

    A += (size_t)blockIdx.z * strideA;
    W += (size_t)blockIdx.z * strideW;
    C += (size_t)blockIdx.z * strideC;

    const int t    = threadIdx.x;
    const int lane = t & 31;
    const int warp = t >> 5;
    const int wm   = warp & 1;       // 0..1
    const int wn   = warp >> 1;      // 0..3
    const int bm   = blockIdx.y * 128;
    const int bn   = blockIdx.x * 128;

    const int qid = lane >> 2;       // 0..7
    const int tig = lane & 3;        // 0..3

    float acc[4][4][4];
#pragma unroll
    for (int mt = 0; mt < 4; mt++)
#pragma unroll
        for (int nt = 0; nt < 4; nt++)
#pragma unroll
            for (int r = 0; r < 4; r++) acc[mt][nt][r] = 0.0f;

    // Loader indexing (per i in 0..3, idx = t + i*256):
    //   A: m = idx&127, kg = idx>>7 (0..7); loads float4 A[bm+m][k0+kg*4]
    //   B: n4 = idx&31, kr = idx>>5 (0..31); loads float4 W[k0+kr][bn+n4*4]

    // Prologue: fill stage 0
    {
#pragma unroll
        for (int i = 0; i < 4; i++) {
            int idx = t + i * 256;
            int m = idx & 127, kg = idx >> 7;
            float4 v = *(const float4*)&A[(size_t)(bm + m) * K + kg * 4];
            AS(0, kg * 4 + 0, m) = f2tf32(v.x);
            AS(0, kg * 4 + 1, m) = f2tf32(v.y);
            AS(0, kg * 4 + 2, m) = f2tf32(v.z);
            AS(0, kg * 4 + 3, m) = f2tf32(v.w);
        }
#pragma unroll
        for (int i = 0; i < 4; i++) {
            int idx = t + i * 256;
            int n4 = idx & 31, kr = idx >> 5;
            float4 v = *(const float4*)&W[(size_t)kr * N + bn + n4 * 4];
            uint4 u;
            u.x = f2tf32(v.x); u.y = f2tf32(v.y);
            u.z = f2tf32(v.z); u.w = f2tf32(v.w);
            *(uint4*)&BS(0, kr, n4 * 4) = u;
        }
    }
    __syncthreads();

    int s = 0;
    for (int k0 = 0; k0 < K; k0 += 32) {
        const bool has_next = (k0 + 32) < K;
        float4 ra[4], rb[4];
        if (has_next) {
            int kn = k0 + 32;
#pragma unroll
            for (int i = 0; i < 4; i++) {
                int idx = t + i * 256;
                int m = idx & 127, kg = idx >> 7;
                ra[i] = *(const float4*)&A[(size_t)(bm + m) * K + kn + kg * 4];
            }
#pragma unroll
            for (int i = 0; i < 4; i++) {
                int idx = t + i * 256;
                int n4 = idx & 31, kr = idx >> 5;
                rb[i] = *(const float4*)&W[(size_t)(kn + kr) * N + bn + n4 * 4];
            }
        }

        // Compute 4 k-steps of k=8 on stage s
#pragma unroll
        for (int ks = 0; ks < 4; ks++) {
            const int kb = ks * 8;
            uint32_t af[4][4];
            uint32_t bf[4][2];
#pragma unroll
            for (int mt = 0; mt < 4; mt++) {
                int r0 = wm * 64 + mt * 16 + qid;
                af[mt][0] = AS(s, kb + tig,     r0);
                af[mt][1] = AS(s, kb + tig,     r0 + 8);
                af[mt][2] = AS(s, kb + tig + 4, r0);
                af[mt][3] = AS(s, kb + tig + 4, r0 + 8);
            }
#pragma unroll
            for (int nt = 0; nt < 4; nt++) {
                int c0 = wn * 32 + nt * 8 + qid;
                bf[nt][0] = BS(s, kb + tig,     c0);
                bf[nt][1] = BS(s, kb + tig + 4, c0);
            }
#pragma unroll
            for (int mt = 0; mt < 4; mt++)
#pragma unroll
                for (int nt = 0; nt < 4; nt++) {
                    asm volatile(
                        "mma.sync.aligned.m16n8k8.row.col.f32.tf32.tf32.f32 "
                        "{%0,%1,%2,%3}, {%4,%5,%6,%7}, {%8,%9}, {%0,%1,%2,%3};\n"
                        : "+f"(acc[mt][nt][0]), "+f"(acc[mt][nt][1]),
                          "+f"(acc[mt][nt][2]), "+f"(acc[mt][nt][3])
                        : "r"(af[mt][0]), "r"(af[mt][1]),
                          "r"(af[mt][2]), "r"(af[mt][3]),
                          "r"(bf[nt][0]), "r"(bf[nt][1]));
                }
        }

        if (has_next) {
            int ns = s ^ 1;
#pragma unroll
            for (int i = 0; i < 4; i++) {
                int idx = t + i * 256;
                int m = idx & 127, kg = idx >> 7;
                AS(ns, kg * 4 + 0, m) = f2tf32(ra[i].x);
                AS(ns, kg * 4 + 1, m) = f2tf32(ra[i].y);
                AS(ns, kg * 4 + 2, m) = f2tf32(ra[i].z);
                AS(ns, kg * 4 + 3, m) = f2tf32(ra[i].w);
            }
#pragma unroll
            for (int i = 0; i < 4; i++) {
                int idx = t + i * 256;
                int n4 = idx & 31, kr = idx >> 5;
                uint4 u;
                u.x = f2tf32(rb[i].x); u.y = f2tf32(rb[i].y);
                u.z = f2tf32(rb[i].z); u.w = f2tf32(rb[i].w);
                *(uint4*)&BS(ns, kr, n4 * 4) = u;
            }
            __syncthreads();
            s = ns;
        }
    }

    // Epilogue: add bias, store. c0/c1 at (row, col*2), c2/c3 at (row+8, col*2).
#pragma unroll
    for (int mt = 0; mt < 4; mt++) {
        int r0 = bm + wm * 64 + mt * 16 + qid;
#pragma unroll
        for (int nt = 0; nt < 4; nt++) {
            int cb = bn + wn * 32 + nt * 8 + tig * 2;
            float b0 = bias[cb], b1 = bias[cb + 1];
            float2 o0, o1;
            o0.x = acc[mt][nt][0] + b0; o0.y = acc[mt][nt][1] + b1;
            o1.x = acc[mt][nt][2] + b0; o1.y = acc[mt][nt][3] + b1;
            *(float2*)&C[(size_t)r0 * N + cb]       = o0;
            *(float2*)&C[(size_t)(r0 + 8) * N + cb] = o1;
        }
    }
#undef AS
#undef BS
}

// ---------------------------------------------------------------------------
// L2-normalize each 64-elem head chunk of Q and K in place (F.normalize, eps=1e-12)
// ---------------------------------------------------------------------------
__global__ __launch_bounds__(256) void l2norm_kernel(float* __restrict__ Q,
                                                     float* __restrict__ K)
{
    const int ngroups = MROWS * HEADS;  // 131072 per tensor
    int wid  = (blockIdx.x * blockDim.x + threadIdx.x) >> 5;
    int lane = threadIdx.x & 31;
    if (wid >= 2 * ngroups) return;
    float* base = (wid < ngroups) ? Q : K;
    int g = (wid < ngroups) ? wid : wid - ngroups;
    float* p = base + (size_t)g * HDIM;

    float2 v = *(float2*)(p + lane * 2);
    float ss = v.x * v.x + v.y * v.y;
#pragma unroll
    for (int o = 16; o > 0; o >>= 1) ss += __shfl_xor_sync(0xFFFFFFFFu, ss, o);
    float nrm = sqrtf(ss);
    float inv = 1.0f / fmaxf(nrm, 1e-12f);
    v.x *= inv; v.y *= inv;
    *(float2*)(p + lane * 2) = v;
}

// ---------------------------------------------------------------------------
// T[b,h] = (K_{b,h}^T @ V_{b,h}) * SEQ^{-sigmoid(m[h])}   -> [64x64] per head
// ---------------------------------------------------------------------------
__global__ __launch_bounds__(256) void ktv_kernel(const float* __restrict__ Kb,
                                                  const float* __restrict__ Vb,
                                                  const float* __restrict__ m,
                                                  float* __restrict__ T)
{
    int bh = blockIdx.x;
    int b = bh >> 4, h = bh & 15;
    __shared__ float Ks[32][64];
    __shared__ float Vs[32][64];
    const int tid = threadIdx.x;
    const int tx = tid & 15, ty = tid >> 4;
    const int lr = tid >> 4;          // 0..15 (rows lr, lr+16)
    const int lc = (tid & 15) * 4;    // 0..60

    const float* Kp = Kb + (size_t)b * SEQ * FEATS + h * HDIM;
    const float* Vp = Vb + (size_t)b * SEQ * FEATS + h * HDIM;

    float acc[4][4];
#pragma unroll
    for (int i = 0; i < 4; i++)
#pragma unroll
        for (int j = 0; j < 4; j++) acc[i][j] = 0.0f;

    for (int j0 = 0; j0 < SEQ; j0 += 32) {
#pragma unroll
        for (int i = 0; i < 2; i++) {
            int r = lr + i * 16;
            *(float4*)&Ks[r][lc] = *(const float4*)&Kp[(size_t)(j0 + r) * FEATS + lc];
            *(float4*)&Vs[r][lc] = *(const float4*)&Vp[(size_t)(j0 + r) * FEATS + lc];
        }
        __syncthreads();
#pragma unroll
        for (int j = 0; j < 32; j++) {
            float ra[4], rb[4];
            *(float4*)ra = *(const float4*)&Ks[j][ty * 4];
            *(float4*)rb = *(const float4*)&Vs[j][tx * 4];
#pragma unroll
            for (int i = 0; i < 4; i++)
#pragma unroll
                for (int c = 0; c < 4; c++)
                    acc[i][c] += ra[i] * rb[c];
        }
        __syncthreads();
    }

    float sig = 1.0f / (1.0f + expf(-m[h]));
    float invscale = powf((float)SEQ, -sig);

#pragma unroll
    for (int i = 0; i < 4; i++) {
        int e = ty * 4 + i;
        float4 o;
        o.x = acc[i][0] * invscale;
        o.y = acc[i][1] * invscale;
        o.z = acc[i][2] * invscale;
        o.w = acc[i][3] * invscale;
        *(float4*)&T[(size_t)bh * 4096 + e * 64 + tx * 4] = o;
    }
}

// ---------------------------------------------------------------------------
// Weff[b][h*64+e][n] = sum_d T[b,h][e][d] * Wo[h*64+d][n]
// ---------------------------------------------------------------------------
__global__ __launch_bounds__(256) void weff_kernel(const float* __restrict__ T,
                                                   const float* __restrict__ Wo,
                                                   float* __restrict__ Weff)
{
    int bh = blockIdx.y;
    int b = bh >> 4, h = bh & 15;
    int n0 = blockIdx.x * 64;
    __shared__ float Tst[64][64];   // Tst[d][e] = T[e][d]
    __shared__ float Ws[64][64];    // Ws[d][nn] = Wo[h*64+d][n0+nn]
    const int tid = threadIdx.x;
    const int lr = tid >> 4;           // 0..15
    const int lc = (tid & 15) * 4;     // 0..60

#pragma unroll
    for (int i = 0; i < 4; i++) {
        int r = lr + i * 16;
        float4 v = *(const float4*)&T[(size_t)bh * 4096 + r * 64 + lc];
        Tst[lc + 0][r] = v.x;
        Tst[lc + 1][r] = v.y;
        Tst[lc + 2][r] = v.z;
        Tst[lc + 3][r] = v.w;
        *(float4*)&Ws[r][lc] = *(const float4*)&Wo[(size_t)(h * HDIM + r) * FEATS + n0 + lc];
    }
    __syncthreads();

    const int tx = tid & 15, ty = tid >> 4;
    float acc[4][4];
#pragma unroll
    for (int i = 0; i < 4; i++)
#pragma unroll
        for (int j = 0; j < 4; j++) acc[i][j] = 0.0f;

#pragma unroll
    for (int d = 0; d < 64; d++) {
        float ra[4], rb[4];
        *(float4*)ra = *(const float4*)&Tst[d][ty * 4];
        *(float4*)rb = *(const float4*)&Ws[d][tx * 4];
#pragma unroll
        for (int i = 0; i < 4; i++)
#pragma unroll
            for (int j = 0; j < 4; j++)
                acc[i][j] += ra[i] * rb[j];
    }

#pragma unroll
    for (int i = 0; i < 4; i++) {
        int e = ty * 4 + i;
        float4 o;
        o.x = acc[i][0]; o.y = acc[i][1]; o.z = acc[i][2]; o.w = acc[i][3];
        *(float4*)&Weff[((size_t)b * FEATS + h * HDIM + e) * FEATS + n0 + tx * 4] = o;
    }
}

// ---------------------------------------------------------------------------
// kernel_launch
// Inputs: x, Wq, bq, Wk, bk, Wv, bv, Wo, bo, m   (all fp32)
// Output: [4, 2048, 1024] fp32
// ---------------------------------------------------------------------------
extern "C" void kernel_launch(void* const* d_in, const int* in_sizes, int n_in,
                              void* d_out, int out_size)
{
    (void)in_sizes; (void)n_in; (void)out_size;
    const float* x  = (const float*)d_in[0];
    const float* Wq = (const float*)d_in[1];
    const float* bq = (const float*)d_in[2];
    const float* Wk = (const float*)d_in[3];
    const float* bk = (const float*)d_in[4];
    const float* Wv = (const float*)d_in[5];
    const float* bv = (const float*)d_in[6];
    const float* Wo = (const float*)d_in[7];
    const float* bo = (const float*)d_in[8];
    const float* m  = (const float*)d_in[9];
    float* out = (float*)d_out;

    float *Q, *K, *V, *T, *Weff;
    cudaGetSymbolAddress((void**)&Q,    g_Q);
    cudaGetSymbolAddress((void**)&K,    g_K);
    cudaGetSymbolAddress((void**)&V,    g_V);
    cudaGetSymbolAddress((void**)&T,    g_T);
    cudaGetSymbolAddress((void**)&Weff, g_Weff);

    const int SMEM_BYTES = 65536;  // 2 stages * (16KB A + 16KB B)
    cudaFuncSetAttribute(gemm_tf32_kernel,
                         cudaFuncAttributeMaxDynamicSharedMemorySize, SMEM_BYTES);

    dim3 blk(256);

    // 1) Q/K/V projections: [8192,1024] @ [1024,1024] on tensor cores (tf32)
    dim3 gqkv(FEATS / 128, MROWS / 128, 1);
    gemm_tf32_kernel<<<gqkv, blk, SMEM_BYTES>>>(x, 0, Wq, 0, bq, Q, 0, MROWS, FEATS, FEATS);
    gemm_tf32_kernel<<<gqkv, blk, SMEM_BYTES>>>(x, 0, Wk, 0, bk, K, 0, MROWS, FEATS, FEATS);
    gemm_tf32_kernel<<<gqkv, blk, SMEM_BYTES>>>(x, 0, Wv, 0, bv, V, 0, MROWS, FEATS, FEATS);

    // 2) L2-normalize Q and K per head chunk (in place).
    {
        int total_warps = 2 * MROWS * HEADS;          // 262144
        int nblocks = total_warps / 8;                // 32768
        l2norm_kernel<<<nblocks, 256>>>(Q, K);
    }

    // 3) T = (K^T V)/scale per (b,h)
    ktv_kernel<<<BATCH * HEADS, blk>>>(K, V, m, T);

    // 4) Fold T into Wo per batch: Weff_b = blockrows(T_bh @ Wo_h)
    weff_kernel<<<dim3(FEATS / 64, BATCH * HEADS), blk>>>(T, Wo, Weff);

    // 5) out_b = Qn_b @ Weff_b + bo  (tensor cores, batched over b)
    dim3 gout(FEATS / 128, SEQ / 128, BATCH);
    gemm_tf32_kernel<<<gout, blk, SMEM_BYTES>>>(Q, (size_t)SEQ * FEATS,
                                                Weff, (size_t)FEATS * FEATS,
                                                bo, out, (size_t)SEQ * FEATS,
                                                SEQ, FEATS, FEATS);
}

// round 6
// speedup vs baseline: 1.6467x; 1.3357x over previous
#include <cuda_runtime.h>
#include <math.h>
#include <stdint.h>

#define BATCH   4
#define SEQ     2048
#define FEATS   1024
#define HEADS   16
#define HDIM    64
#define MROWS   (BATCH*SEQ)   // 8192

// Scratch (device globals: allocation-free rule)
__device__ float g_Q[MROWS*FEATS];                 // 32 MB (normalized in place)
__device__ float g_K[MROWS*FEATS];                 // 32 MB (normalized in place)
__device__ float g_V[MROWS*FEATS];                 // 32 MB
__device__ float g_T[BATCH*HEADS*HDIM*HDIM];       // 1 MB  : (K^T V)/scale per (b,h)
__device__ float g_Weff[BATCH*FEATS*FEATS];        // 16 MB : per-batch folded T*Wo

__device__ __forceinline__ uint32_t f2tf32(float f) {
    uint32_t u;
    asm("cvt.rna.tf32.f32 %0, %1;" : "=r"(u) : "f"(f));
    return u;
}

// ---------------------------------------------------------------------------
// TF32 tensor-core GEMM: C[z] = A[z] @ W[z] + bias
// A row-major [M,K], W row-major [K,N]. BM=128 BN=128 BK=32.
// 256 threads = 8 warps (2 warp-m x 4 warp-n), warp tile 64x32, m16n8k8 mma.
// Double-buffered dynamic smem: As[2][32][128+pad], Bs[2][32][128+pad].
// Row stride 132 words => bank = (4k + m) mod 32: the 4 lanes with tig=0..3
// (different k) land on banks offset by 4,8,12 -> all 32 lanes distinct banks.
// ---------------------------------------------------------------------------
#define LDPAD  132                       // 128 + 4 words
#define STG_W  (32*LDPAD)                // words per stage = 4224

__global__ __launch_bounds__(256) void gemm_tf32_kernel(
    const float* __restrict__ A, size_t strideA,
    const float* __restrict__ W, size_t strideW,
    const float* __restrict__ bias,
    float* __restrict__ C, size_t strideC,
    int M, int N, int K)
{
    extern __shared__ uint32_t smem_u[];
    // As at [0, 2*STG_W) words, Bs at [2*STG_W, 4*STG_W)
#define AS(st,k,mm) smem_u[(st)*STG_W + (k)*LDPAD + (mm)]
#define BS(st,k,nn) smem_u[2*STG_W + (st)*STG_W + (k)*LDPAD + (nn)]

    A += (size_t)blockIdx.z * strideA;
    W += (size_t)blockIdx.z * strideW;
    C += (size_t)blockIdx.z * strideC;

    const int t    = threadIdx.x;
    const int lane = t & 31;
    const int warp = t >> 5;
    const int wm   = warp & 1;       // 0..1
    const int wn   = warp >> 1;      // 0..3
    const int bm   = blockIdx.y * 128;
    const int bn   = blockIdx.x * 128;

    const int qid = lane >> 2;       // 0..7
    const int tig = lane & 3;        // 0..3

    float acc[4][4][4];
#pragma unroll
    for (int mt = 0; mt < 4; mt++)
#pragma unroll
        for (int nt = 0; nt < 4; nt++)
#pragma unroll
            for (int r = 0; r < 4; r++) acc[mt][nt][r] = 0.0f;

    // Loader indexing (per i in 0..3, idx = t + i*256):
    //   A: m = idx&127, kg = idx>>7 (0..7); loads float4 A[bm+m][k0+kg*4]
    //   B: n4 = idx&31, kr = idx>>5 (0..31); loads float4 W[k0+kr][bn+n4*4]

    // Prologue: fill stage 0
    {
#pragma unroll
        for (int i = 0; i < 4; i++) {
            int idx = t + i * 256;
            int m = idx & 127, kg = idx >> 7;
            float4 v = *(const float4*)&A[(size_t)(bm + m) * K + kg * 4];
            AS(0, kg * 4 + 0, m) = f2tf32(v.x);
            AS(0, kg * 4 + 1, m) = f2tf32(v.y);
            AS(0, kg * 4 + 2, m) = f2tf32(v.z);
            AS(0, kg * 4 + 3, m) = f2tf32(v.w);
        }
#pragma unroll
        for (int i = 0; i < 4; i++) {
            int idx = t + i * 256;
            int n4 = idx & 31, kr = idx >> 5;
            float4 v = *(const float4*)&W[(size_t)kr * N + bn + n4 * 4];
            uint4 u;
            u.x = f2tf32(v.x); u.y = f2tf32(v.y);
            u.z = f2tf32(v.z); u.w = f2tf32(v.w);
            *(uint4*)&BS(0, kr, n4 * 4) = u;
        }
    }
    __syncthreads();

    int s = 0;
    for (int k0 = 0; k0 < K; k0 += 32) {
        const bool has_next = (k0 + 32) < K;
        float4 ra[4], rb[4];
        if (has_next) {
            int kn = k0 + 32;
#pragma unroll
            for (int i = 0; i < 4; i++) {
                int idx = t + i * 256;
                int m = idx & 127, kg = idx >> 7;
                ra[i] = *(const float4*)&A[(size_t)(bm + m) * K + kn + kg * 4];
            }
#pragma unroll
            for (int i = 0; i < 4; i++) {
                int idx = t + i * 256;
                int n4 = idx & 31, kr = idx >> 5;
                rb[i] = *(const float4*)&W[(size_t)(kn + kr) * N + bn + n4 * 4];
            }
        }

        // Compute 4 k-steps of k=8 on stage s
#pragma unroll
        for (int ks = 0; ks < 4; ks++) {
            const int kb = ks * 8;
            uint32_t af[4][4];
            uint32_t bf[4][2];
#pragma unroll
            for (int mt = 0; mt < 4; mt++) {
                int r0 = wm * 64 + mt * 16 + qid;
                af[mt][0] = AS(s, kb + tig,     r0);
                af[mt][1] = AS(s, kb + tig,     r0 + 8);
                af[mt][2] = AS(s, kb + tig + 4, r0);
                af[mt][3] = AS(s, kb + tig + 4, r0 + 8);
            }
#pragma unroll
            for (int nt = 0; nt < 4; nt++) {
                int c0 = wn * 32 + nt * 8 + qid;
                bf[nt][0] = BS(s, kb + tig,     c0);
                bf[nt][1] = BS(s, kb + tig + 4, c0);
            }
#pragma unroll
            for (int mt = 0; mt < 4; mt++)
#pragma unroll
                for (int nt = 0; nt < 4; nt++) {
                    asm volatile(
                        "mma.sync.aligned.m16n8k8.row.col.f32.tf32.tf32.f32 "
                        "{%0,%1,%2,%3}, {%4,%5,%6,%7}, {%8,%9}, {%0,%1,%2,%3};\n"
                        : "+f"(acc[mt][nt][0]), "+f"(acc[mt][nt][1]),
                          "+f"(acc[mt][nt][2]), "+f"(acc[mt][nt][3])
                        : "r"(af[mt][0]), "r"(af[mt][1]),
                          "r"(af[mt][2]), "r"(af[mt][3]),
                          "r"(bf[nt][0]), "r"(bf[nt][1]));
                }
        }

        if (has_next) {
            int ns = s ^ 1;
#pragma unroll
            for (int i = 0; i < 4; i++) {
                int idx = t + i * 256;
                int m = idx & 127, kg = idx >> 7;
                AS(ns, kg * 4 + 0, m) = f2tf32(ra[i].x);
                AS(ns, kg * 4 + 1, m) = f2tf32(ra[i].y);
                AS(ns, kg * 4 + 2, m) = f2tf32(ra[i].z);
                AS(ns, kg * 4 + 3, m) = f2tf32(ra[i].w);
            }
#pragma unroll
            for (int i = 0; i < 4; i++) {
                int idx = t + i * 256;
                int n4 = idx & 31, kr = idx >> 5;
                uint4 u;
                u.x = f2tf32(rb[i].x); u.y = f2tf32(rb[i].y);
                u.z = f2tf32(rb[i].z); u.w = f2tf32(rb[i].w);
                *(uint4*)&BS(ns, kr, n4 * 4) = u;
            }
            __syncthreads();
            s = ns;
        }
    }

    // Epilogue: add bias, store. c0/c1 at (row, col*2), c2/c3 at (row+8, col*2).
#pragma unroll
    for (int mt = 0; mt < 4; mt++) {
        int r0 = bm + wm * 64 + mt * 16 + qid;
#pragma unroll
        for (int nt = 0; nt < 4; nt++) {
            int cb = bn + wn * 32 + nt * 8 + tig * 2;
            float b0 = bias[cb], b1 = bias[cb + 1];
            float2 o0, o1;
            o0.x = acc[mt][nt][0] + b0; o0.y = acc[mt][nt][1] + b1;
            o1.x = acc[mt][nt][2] + b0; o1.y = acc[mt][nt][3] + b1;
            *(float2*)&C[(size_t)r0 * N + cb]       = o0;
            *(float2*)&C[(size_t)(r0 + 8) * N + cb] = o1;
        }
    }
#undef AS
#undef BS
}

// ---------------------------------------------------------------------------
// L2-normalize each 64-elem head chunk of Q and K in place (F.normalize, eps=1e-12)
// ---------------------------------------------------------------------------
__global__ __launch_bounds__(256) void l2norm_kernel(float* __restrict__ Q,
                                                     float* __restrict__ K)
{
    const int ngroups = MROWS * HEADS;  // 131072 per tensor
    int wid  = (blockIdx.x * blockDim.x + threadIdx.x) >> 5;
    int lane = threadIdx.x & 31;
    if (wid >= 2 * ngroups) return;
    float* base = (wid < ngroups) ? Q : K;
    int g = (wid < ngroups) ? wid : wid - ngroups;
    float* p = base + (size_t)g * HDIM;

    float2 v = *(float2*)(p + lane * 2);
    float ss = v.x * v.x + v.y * v.y;
#pragma unroll
    for (int o = 16; o > 0; o >>= 1) ss += __shfl_xor_sync(0xFFFFFFFFu, ss, o);
    float nrm = sqrtf(ss);
    float inv = 1.0f / fmaxf(nrm, 1e-12f);
    v.x *= inv; v.y *= inv;
    *(float2*)(p + lane * 2) = v;
}

// ---------------------------------------------------------------------------
// T[b,h] = (K_{b,h}^T @ V_{b,h}) * SEQ^{-sigmoid(m[h])}   -> [64x64] per head
// ---------------------------------------------------------------------------
__global__ __launch_bounds__(256) void ktv_kernel(const float* __restrict__ Kb,
                                                  const float* __restrict__ Vb,
                                                  const float* __restrict__ m,
                                                  float* __restrict__ T)
{
    int bh = blockIdx.x;
    int b = bh >> 4, h = bh & 15;
    __shared__ float Ks[32][64];
    __shared__ float Vs[32][64];
    const int tid = threadIdx.x;
    const int tx = tid & 15, ty = tid >> 4;
    const int lr = tid >> 4;          // 0..15 (rows lr, lr+16)
    const int lc = (tid & 15) * 4;    // 0..60

    const float* Kp = Kb + (size_t)b * SEQ * FEATS + h * HDIM;
    const float* Vp = Vb + (size_t)b * SEQ * FEATS + h * HDIM;

    float acc[4][4];
#pragma unroll
    for (int i = 0; i < 4; i++)
#pragma unroll
        for (int j = 0; j < 4; j++) acc[i][j] = 0.0f;

    for (int j0 = 0; j0 < SEQ; j0 += 32) {
#pragma unroll
        for (int i = 0; i < 2; i++) {
            int r = lr + i * 16;
            *(float4*)&Ks[r][lc] = *(const float4*)&Kp[(size_t)(j0 + r) * FEATS + lc];
            *(float4*)&Vs[r][lc] = *(const float4*)&Vp[(size_t)(j0 + r) * FEATS + lc];
        }
        __syncthreads();
#pragma unroll
        for (int j = 0; j < 32; j++) {
            float ra[4], rb[4];
            *(float4*)ra = *(const float4*)&Ks[j][ty * 4];
            *(float4*)rb = *(const float4*)&Vs[j][tx * 4];
#pragma unroll
            for (int i = 0; i < 4; i++)
#pragma unroll
                for (int c = 0; c < 4; c++)
                    acc[i][c] += ra[i] * rb[c];
        }
        __syncthreads();
    }

    float sig = 1.0f / (1.0f + expf(-m[h]));
    float invscale = powf((float)SEQ, -sig);

#pragma unroll
    for (int i = 0; i < 4; i++) {
        int e = ty * 4 + i;
        float4 o;
        o.x = acc[i][0] * invscale;
        o.y = acc[i][1] * invscale;
        o.z = acc[i][2] * invscale;
        o.w = acc[i][3] * invscale;
        *(float4*)&T[(size_t)bh * 4096 + e * 64 + tx * 4] = o;
    }
}

// ---------------------------------------------------------------------------
// Weff[b][h*64+e][n] = sum_d T[b,h][e][d] * Wo[h*64+d][n]
// ---------------------------------------------------------------------------
__global__ __launch_bounds__(256) void weff_kernel(const float* __restrict__ T,
                                                   const float* __restrict__ Wo,
                                                   float* __restrict__ Weff)
{
    int bh = blockIdx.y;
    int b = bh >> 4, h = bh & 15;
    int n0 = blockIdx.x * 64;
    __shared__ float Tst[64][64];   // Tst[d][e] = T[e][d]
    __shared__ float Ws[64][64];    // Ws[d][nn] = Wo[h*64+d][n0+nn]
    const int tid = threadIdx.x;
    const int lr = tid >> 4;           // 0..15
    const int lc = (tid & 15) * 4;     // 0..60

#pragma unroll
    for (int i = 0; i < 4; i++) {
        int r = lr + i * 16;
        float4 v = *(const float4*)&T[(size_t)bh * 4096 + r * 64 + lc];
        Tst[lc + 0][r] = v.x;
        Tst[lc + 1][r] = v.y;
        Tst[lc + 2][r] = v.z;
        Tst[lc + 3][r] = v.w;
        *(float4*)&Ws[r][lc] = *(const float4*)&Wo[(size_t)(h * HDIM + r) * FEATS + n0 + lc];
    }
    __syncthreads();

    const int tx = tid & 15, ty = tid >> 4;
    float acc[4][4];
#pragma unroll
    for (int i = 0; i < 4; i++)
#pragma unroll
        for (int j = 0; j < 4; j++) acc[i][j] = 0.0f;

#pragma unroll
    for (int d = 0; d < 64; d++) {
        float ra[4], rb[4];
        *(float4*)ra = *(const float4*)&Tst[d][ty * 4];
        *(float4*)rb = *(const float4*)&Ws[d][tx * 4];
#pragma unroll
        for (int i = 0; i < 4; i++)
#pragma unroll
            for (int j = 0; j < 4; j++)
                acc[i][j] += ra[i] * rb[j];
    }

#pragma unroll
    for (int i = 0; i < 4; i++) {
        int e = ty * 4 + i;
        float4 o;
        o.x = acc[i][0]; o.y = acc[i][1]; o.z = acc[i][2]; o.w = acc[i][3];
        *(float4*)&Weff[((size_t)b * FEATS + h * HDIM + e) * FEATS + n0 + tx * 4] = o;
    }
}

// ---------------------------------------------------------------------------
// kernel_launch
// Inputs: x, Wq, bq, Wk, bk, Wv, bv, Wo, bo, m   (all fp32)
// Output: [4, 2048, 1024] fp32
// ---------------------------------------------------------------------------
extern "C" void kernel_launch(void* const* d_in, const int* in_sizes, int n_in,
                              void* d_out, int out_size)
{
    (void)in_sizes; (void)n_in; (void)out_size;
    const float* x  = (const float*)d_in[0];
    const float* Wq = (const float*)d_in[1];
    const float* bq = (const float*)d_in[2];
    const float* Wk = (const float*)d_in[3];
    const float* bk = (const float*)d_in[4];
    const float* Wv = (const float*)d_in[5];
    const float* bv = (const float*)d_in[6];
    const float* Wo = (const float*)d_in[7];
    const float* bo = (const float*)d_in[8];
    const float* m  = (const float*)d_in[9];
    float* out = (float*)d_out;

    float *Q, *K, *V, *T, *Weff;
    cudaGetSymbolAddress((void**)&Q,    g_Q);
    cudaGetSymbolAddress((void**)&K,    g_K);
    cudaGetSymbolAddress((void**)&V,    g_V);
    cudaGetSymbolAddress((void**)&T,    g_T);
    cudaGetSymbolAddress((void**)&Weff, g_Weff);

    const int SMEM_BYTES = 4 * STG_W * 4;  // 2 stages * (A + B) * 4224 words = 67584 B
    cudaFuncSetAttribute(gemm_tf32_kernel,
                         cudaFuncAttributeMaxDynamicSharedMemorySize, SMEM_BYTES);

    dim3 blk(256);

    // 1) Q/K/V projections: [8192,1024] @ [1024,1024] on tensor cores (tf32)
    dim3 gqkv(FEATS / 128, MROWS / 128, 1);
    gemm_tf32_kernel<<<gqkv, blk, SMEM_BYTES>>>(x, 0, Wq, 0, bq, Q, 0, MROWS, FEATS, FEATS);
    gemm_tf32_kernel<<<gqkv, blk, SMEM_BYTES>>>(x, 0, Wk, 0, bk, K, 0, MROWS, FEATS, FEATS);
    gemm_tf32_kernel<<<gqkv, blk, SMEM_BYTES>>>(x, 0, Wv, 0, bv, V, 0, MROWS, FEATS, FEATS);

    // 2) L2-normalize Q and K per head chunk (in place).
    {
        int total_warps = 2 * MROWS * HEADS;          // 262144
        int nblocks = total_warps / 8;                // 32768
        l2norm_kernel<<<nblocks, 256>>>(Q, K);
    }

    // 3) T = (K^T V)/scale per (b,h)
    ktv_kernel<<<BATCH * HEADS, blk>>>(K, V, m, T);

    // 4) Fold T into Wo per batch: Weff_b = blockrows(T_bh @ Wo_h)
    weff_kernel<<<dim3(FEATS / 64, BATCH * HEADS), blk>>>(T, Wo, Weff);

    // 5) out_b = Qn_b @ Weff_b + bo  (tensor cores, batched over b)
    dim3 gout(FEATS / 128, SEQ / 128, BATCH);
    gemm_tf32_kernel<<<gout, blk, SMEM_BYTES>>>(Q, (size_t)SEQ * FEATS,
                                                Weff, (size_t)FEATS * FEATS,
                                                bo, out, (size_t)SEQ * FEATS,
                                                SEQ, FEATS, FEATS);
}

// round 10
// speedup vs baseline: 1.7612x; 1.0695x over previous
#include <cuda_runtime.h>
#include <math.h>
#include <stdint.h>

#define BATCH   4
#define SEQ     2048
#define FEATS   1024
#define HEADS   16
#define HDIM    64
#define MROWS   (BATCH*SEQ)   // 8192

// Scratch (device globals: allocation-free rule)
__device__ float g_Q[MROWS*FEATS];
__device__ float g_K[MROWS*FEATS];
__device__ float g_V[MROWS*FEATS];
__device__ float g_T[BATCH*HEADS*HDIM*HDIM];
__device__ float g_Weff[BATCH*FEATS*FEATS];

__device__ __forceinline__ uint32_t f2tf32(float f) {
    uint32_t u;
    asm("cvt.rna.tf32.f32 %0, %1;" : "=r"(u) : "f"(f));
    return u;
}

// ---------------------------------------------------------------------------
// TF32 mma.sync GEMM with FRAGMENT-ORDERED smem.
// C[z] = A[z] @ W[z] + bias. A row-major [M,K], W row-major [K,N].
// BM=BN=128, BK=32. 256 threads = 8 warps (2 wm x 4 wn), warp tile 64x32.
//
// Smem layout (per stage):
//  A fragments: 32 blocks (ks 0..3  x mfrag 0..7), 512 B each = 16 KB.
//    block word = (lane*4 + slot) with chunk-XOR swizzle; slot = 2*rowhalf + khalf.
//    -> compute loads one LDS.128 per (ks, mt): regs {a0,a2,a1,a3}.
//  B fragments: 64 blocks (nfrag 0..15 x ks 0..3, f = nfrag*4+ks), 288 B each
//    (256 data + 32 pad) = 18 KB. block word = lane*2 + khalf.
//    -> compute loads one LDS.64 per (ks, nt).
// ---------------------------------------------------------------------------
#define A_STG_B   16384
#define B_STG_B   18432
#define OFF_A0    0
#define OFF_A1    A_STG_B
#define OFF_B0    (2*A_STG_B)
#define OFF_B1    (2*A_STG_B + B_STG_B)
#define SMEM_TOT  (2*A_STG_B + 2*B_STG_B)   // 69632 bytes

__device__ __forceinline__ void store_A_frag(char* abase, int m, int ksA,
                                             const float4& r0, const float4& r1)
{
    // r0 = A[m][8*ksA + 0..3] (khalf 0), r1 = +4..7 (khalf 1)
    float v0[4] = { r0.x, r0.y, r0.z, r0.w };
    float v1[4] = { r1.x, r1.y, r1.z, r1.w };
    const int mf = m >> 4;
    const int b3 = (m >> 3) & 1;
    char* blk = abase + ((ksA * 8 + mf) << 9);
#pragma unroll
    for (int tg = 0; tg < 4; tg++) {
        int lst = (m & 7) * 4 + tg;
        uint32_t off = (uint32_t)(((lst * 16) ^ ((lst & 24) << 1)) + b3 * 8);
        uint2 u;
        u.x = f2tf32(v0[tg]);   // slot 2*b3+0 : khalf 0
        u.y = f2tf32(v1[tg]);   // slot 2*b3+1 : khalf 1
        *(uint2*)(blk + off) = u;
    }
}

__device__ __forceinline__ void store_B_frag(char* bbase, int krow, int nbase,
                                             const float4* rb)
{
    const int ksB = krow >> 3;
    const int tg  = krow & 3;
    const int kh  = (krow >> 2) & 1;
#pragma unroll
    for (int j = 0; j < 4; j++) {
        float vv[4] = { rb[j].x, rb[j].y, rb[j].z, rb[j].w };
#pragma unroll
        for (int jj = 0; jj < 4; jj++) {
            int n = nbase + j * 4 + jj;
            uint32_t off = (uint32_t)((((n >> 3) * 4 + ksB) * 288) +
                                      (n & 7) * 32 + tg * 8 + kh * 4);
            *(uint32_t*)(bbase + off) = f2tf32(vv[jj]);
        }
    }
}

__global__ __launch_bounds__(256) void gemm_tf32_kernel(
    const float* __restrict__ A, size_t strideA,
    const float* __restrict__ W, size_t strideW,
    const float* __restrict__ bias,
    float* __restrict__ C, size_t strideC,
    int M, int N, int K)
{
    extern __shared__ char smem[];

    A += (size_t)blockIdx.z * strideA;
    W += (size_t)blockIdx.z * strideW;
    C += (size_t)blockIdx.z * strideC;

    const int t    = threadIdx.x;
    const int lane = t & 31;
    const int warp = t >> 5;
    const int wm   = warp & 1;
    const int wn   = warp >> 1;
    const int bm   = blockIdx.y * 128;
    const int bn   = blockIdx.x * 128;
    const int qd   = lane >> 2;
    const int tg   = lane & 3;
    const uint32_t achunk = (uint32_t)((lane * 16) ^ ((lane & 24) << 1));

    // Loader assignments
    const int m0 = t & 127,          ksA0 = t >> 7;          // A pair j=0
    const int m1 = (t + 256) & 127,  ksA1 = (t + 256) >> 7;  // A pair j=1
    const int bl = lane;                                      // B k-row
    const int bw = warp;                                      // B n-group of 16

    float acc[4][4][4];
#pragma unroll
    for (int mt = 0; mt < 4; mt++)
#pragma unroll
        for (int nt = 0; nt < 4; nt++)
#pragma unroll
            for (int r = 0; r < 4; r++) acc[mt][nt][r] = 0.0f;

    // Prologue: fill stage 0 (k0 = 0)
    {
        float4 a00 = *(const float4*)&A[(size_t)(bm + m0) * K + ksA0 * 8];
        float4 a01 = *(const float4*)&A[(size_t)(bm + m0) * K + ksA0 * 8 + 4];
        float4 a10 = *(const float4*)&A[(size_t)(bm + m1) * K + ksA1 * 8];
        float4 a11 = *(const float4*)&A[(size_t)(bm + m1) * K + ksA1 * 8 + 4];
        float4 rb[4];
        const float* wp = &W[(size_t)bl * N + bn + bw * 16];
#pragma unroll
        for (int j = 0; j < 4; j++) rb[j] = *(const float4*)&wp[j * 4];

        store_A_frag(smem + OFF_A0, m0, ksA0, a00, a01);
        store_A_frag(smem + OFF_A0, m1, ksA1, a10, a11);
        store_B_frag(smem + OFF_B0, bl, bw * 16, rb);
    }
    __syncthreads();

    int s = 0;
    for (int k0 = 0; k0 < K; k0 += 32) {
        const bool has_next = (k0 + 32) < K;
        float4 pa[4], pb[4];
        if (has_next) {
            const int kn = k0 + 32;
            pa[0] = *(const float4*)&A[(size_t)(bm + m0) * K + kn + ksA0 * 8];
            pa[1] = *(const float4*)&A[(size_t)(bm + m0) * K + kn + ksA0 * 8 + 4];
            pa[2] = *(const float4*)&A[(size_t)(bm + m1) * K + kn + ksA1 * 8];
            pa[3] = *(const float4*)&A[(size_t)(bm + m1) * K + kn + ksA1 * 8 + 4];
            const float* wp = &W[(size_t)(kn + bl) * N + bn + bw * 16];
#pragma unroll
            for (int j = 0; j < 4; j++) pb[j] = *(const float4*)&wp[j * 4];
        }

        char* ab = smem + (s ? OFF_A1 : OFF_A0);
        char* bb = smem + (s ? OFF_B1 : OFF_B0);

#pragma unroll
        for (int ks = 0; ks < 4; ks++) {
            uint4 aq[4];
            uint2 bq[4];
#pragma unroll
            for (int mt = 0; mt < 4; mt++)
                aq[mt] = *(const uint4*)(ab + ((ks * 8 + wm * 4 + mt) << 9) + achunk);
#pragma unroll
            for (int nt = 0; nt < 4; nt++)
                bq[nt] = *(const uint2*)(bb + ((wn * 4 + nt) * 4 + ks) * 288 + lane * 8);
#pragma unroll
            for (int mt = 0; mt < 4; mt++)
#pragma unroll
                for (int nt = 0; nt < 4; nt++) {
                    // reg order from slot layout: a0=q.x, a1=q.z, a2=q.y, a3=q.w
                    asm volatile(
                        "mma.sync.aligned.m16n8k8.row.col.f32.tf32.tf32.f32 "
                        "{%0,%1,%2,%3}, {%4,%5,%6,%7}, {%8,%9}, {%0,%1,%2,%3};\n"
                        : "+f"(acc[mt][nt][0]), "+f"(acc[mt][nt][1]),
                          "+f"(acc[mt][nt][2]), "+f"(acc[mt][nt][3])
                        : "r"(aq[mt].x), "r"(aq[mt].z),
                          "r"(aq[mt].y), "r"(aq[mt].w),
                          "r"(bq[nt].x), "r"(bq[nt].y));
                }
        }

        if (has_next) {
            char* nab = smem + (s ? OFF_A0 : OFF_A1);
            char* nbb = smem + (s ? OFF_B0 : OFF_B1);
            store_A_frag(nab, m0, ksA0, pa[0], pa[1]);
            store_A_frag(nab, m1, ksA1, pa[2], pa[3]);
            store_B_frag(nbb, bl, bw * 16, pb);
            __syncthreads();
            s ^= 1;
        }
    }

    // Epilogue: add bias, store. c0/c1 at (row, col*2), c2/c3 at (row+8, col*2).
#pragma unroll
    for (int mt = 0; mt < 4; mt++) {
        int r0 = bm + wm * 64 + mt * 16 + qd;
#pragma unroll
        for (int nt = 0; nt < 4; nt++) {
            int cb = bn + wn * 32 + nt * 8 + tg * 2;
            float b0 = bias[cb], b1 = bias[cb + 1];
            float2 o0, o1;
            o0.x = acc[mt][nt][0] + b0; o0.y = acc[mt][nt][1] + b1;
            o1.x = acc[mt][nt][2] + b0; o1.y = acc[mt][nt][3] + b1;
            *(float2*)&C[(size_t)r0 * N + cb]       = o0;
            *(float2*)&C[(size_t)(r0 + 8) * N + cb] = o1;
        }
    }
}

// ---------------------------------------------------------------------------
// L2-normalize each 64-elem head chunk of Q and K in place (F.normalize, eps=1e-12)
// ---------------------------------------------------------------------------
__global__ __launch_bounds__(256) void l2norm_kernel(float* __restrict__ Q,
                                                     float* __restrict__ K)
{
    const int ngroups = MROWS * HEADS;
    int wid  = (blockIdx.x * blockDim.x + threadIdx.x) >> 5;
    int lane = threadIdx.x & 31;
    if (wid >= 2 * ngroups) return;
    float* base = (wid < ngroups) ? Q : K;
    int g = (wid < ngroups) ? wid : wid - ngroups;
    float* p = base + (size_t)g * HDIM;

    float2 v = *(float2*)(p + lane * 2);
    float ss = v.x * v.x + v.y * v.y;
#pragma unroll
    for (int o = 16; o > 0; o >>= 1) ss += __shfl_xor_sync(0xFFFFFFFFu, ss, o);
    float nrm = sqrtf(ss);
    float inv = 1.0f / fmaxf(nrm, 1e-12f);
    v.x *= inv; v.y *= inv;
    *(float2*)(p + lane * 2) = v;
}

// ---------------------------------------------------------------------------
// T[b,h] = (K_{b,h}^T @ V_{b,h}) * SEQ^{-sigmoid(m[h])}
// ---------------------------------------------------------------------------
__global__ __launch_bounds__(256) void ktv_kernel(const float* __restrict__ Kb,
                                                  const float* __restrict__ Vb,
                                                  const float* __restrict__ m,
                                                  float* __restrict__ T)
{
    int bh = blockIdx.x;
    int b = bh >> 4, h = bh & 15;
    __shared__ float Ks[32][64];
    __shared__ float Vs[32][64];
    const int tid = threadIdx.x;
    const int tx = tid & 15, ty = tid >> 4;
    const int lr = tid >> 4;
    const int lc = (tid & 15) * 4;

    const float* Kp = Kb + (size_t)b * SEQ * FEATS + h * HDIM;
    const float* Vp = Vb + (size_t)b * SEQ * FEATS + h * HDIM;

    float acc[4][4];
#pragma unroll
    for (int i = 0; i < 4; i++)
#pragma unroll
        for (int j = 0; j < 4; j++) acc[i][j] = 0.0f;

    for (int j0 = 0; j0 < SEQ; j0 += 32) {
#pragma unroll
        for (int i = 0; i < 2; i++) {
            int r = lr + i * 16;
            *(float4*)&Ks[r][lc] = *(const float4*)&Kp[(size_t)(j0 + r) * FEATS + lc];
            *(float4*)&Vs[r][lc] = *(const float4*)&Vp[(size_t)(j0 + r) * FEATS + lc];
        }
        __syncthreads();
#pragma unroll
        for (int j = 0; j < 32; j++) {
            float ra[4], rb[4];
            *(float4*)ra = *(const float4*)&Ks[j][ty * 4];
            *(float4*)rb = *(const float4*)&Vs[j][tx * 4];
#pragma unroll
            for (int i = 0; i < 4; i++)
#pragma unroll
                for (int c = 0; c < 4; c++)
                    acc[i][c] += ra[i] * rb[c];
        }
        __syncthreads();
    }

    float sig = 1.0f / (1.0f + expf(-m[h]));
    float invscale = powf((float)SEQ, -sig);

#pragma unroll
    for (int i = 0; i < 4; i++) {
        int e = ty * 4 + i;
        float4 o;
        o.x = acc[i][0] * invscale;
        o.y = acc[i][1] * invscale;
        o.z = acc[i][2] * invscale;
        o.w = acc[i][3] * invscale;
        *(float4*)&T[(size_t)bh * 4096 + e * 64 + tx * 4] = o;
    }
}

// ---------------------------------------------------------------------------
// Weff[b][h*64+e][n] = sum_d T[b,h][e][d] * Wo[h*64+d][n]
// ---------------------------------------------------------------------------
__global__ __launch_bounds__(256) void weff_kernel(const float* __restrict__ T,
                                                   const float* __restrict__ Wo,
                                                   float* __restrict__ Weff)
{
    int bh = blockIdx.y;
    int b = bh >> 4, h = bh & 15;
    int n0 = blockIdx.x * 64;
    __shared__ float Tst[64][64];
    __shared__ float Ws[64][64];
    const int tid = threadIdx.x;
    const int lr = tid >> 4;
    const int lc = (tid & 15) * 4;

#pragma unroll
    for (int i = 0; i < 4; i++) {
        int r = lr + i * 16;
        float4 v = *(const float4*)&T[(size_t)bh * 4096 + r * 64 + lc];
        Tst[lc + 0][r] = v.x;
        Tst[lc + 1][r] = v.y;
        Tst[lc + 2][r] = v.z;
        Tst[lc + 3][r] = v.w;
        *(float4*)&Ws[r][lc] = *(const float4*)&Wo[(size_t)(h * HDIM + r) * FEATS + n0 + lc];
    }
    __syncthreads();

    const int tx = tid & 15, ty = tid >> 4;
    float acc[4][4];
#pragma unroll
    for (int i = 0; i < 4; i++)
#pragma unroll
        for (int j = 0; j < 4; j++) acc[i][j] = 0.0f;

#pragma unroll
    for (int d = 0; d < 64; d++) {
        float ra[4], rb[4];
        *(float4*)ra = *(const float4*)&Tst[d][ty * 4];
        *(float4*)rb = *(const float4*)&Ws[d][tx * 4];
#pragma unroll
        for (int i = 0; i < 4; i++)
#pragma unroll
            for (int j = 0; j < 4; j++)
                acc[i][j] += ra[i] * rb[j];
    }

#pragma unroll
    for (int i = 0; i < 4; i++) {
        int e = ty * 4 + i;
        float4 o;
        o.x = acc[i][0]; o.y = acc[i][1]; o.z = acc[i][2]; o.w = acc[i][3];
        *(float4*)&Weff[((size_t)b * FEATS + h * HDIM + e) * FEATS + n0 + tx * 4] = o;
    }
}

// ---------------------------------------------------------------------------
// kernel_launch
// ---------------------------------------------------------------------------
extern "C" void kernel_launch(void* const* d_in, const int* in_sizes, int n_in,
                              void* d_out, int out_size)
{
    (void)in_sizes; (void)n_in; (void)out_size;
    const float* x  = (const float*)d_in[0];
    const float* Wq = (const float*)d_in[1];
    const float* bq = (const float*)d_in[2];
    const float* Wk = (const float*)d_in[3];
    const float* bk = (const float*)d_in[4];
    const float* Wv = (const float*)d_in[5];
    const float* bv = (const float*)d_in[6];
    const float* Wo = (const float*)d_in[7];
    const float* bo = (const float*)d_in[8];
    const float* m  = (const float*)d_in[9];
    float* out = (float*)d_out;

    float *Q, *K, *V, *T, *Weff;
    cudaGetSymbolAddress((void**)&Q,    g_Q);
    cudaGetSymbolAddress((void**)&K,    g_K);
    cudaGetSymbolAddress((void**)&V,    g_V);
    cudaGetSymbolAddress((void**)&T,    g_T);
    cudaGetSymbolAddress((void**)&Weff, g_Weff);

    cudaFuncSetAttribute(gemm_tf32_kernel,
                         cudaFuncAttributeMaxDynamicSharedMemorySize, SMEM_TOT);

    dim3 blk(256);

    // 1) Q/K/V projections: tensor cores (tf32 mma.sync), fragment-ordered smem
    dim3 gqkv(FEATS / 128, MROWS / 128, 1);
    gemm_tf32_kernel<<<gqkv, blk, SMEM_TOT>>>(x, 0, Wq, 0, bq, Q, 0, MROWS, FEATS, FEATS);
    gemm_tf32_kernel<<<gqkv, blk, SMEM_TOT>>>(x, 0, Wk, 0, bk, K, 0, MROWS, FEATS, FEATS);
    gemm_tf32_kernel<<<gqkv, blk, SMEM_TOT>>>(x, 0, Wv, 0, bv, V, 0, MROWS, FEATS, FEATS);

    // 2) L2-normalize Q and K per head chunk (in place).
    {
        int total_warps = 2 * MROWS * HEADS;          // 262144
        int nblocks = total_warps / 8;                // 32768
        l2norm_kernel<<<nblocks, 256>>>(Q, K);
    }

    // 3) T = (K^T V)/scale per (b,h)
    ktv_kernel<<<BATCH * HEADS, blk>>>(K, V, m, T);

    // 4) Weff_b = blockrows(T_bh @ Wo_h)
    weff_kernel<<<dim3(FEATS / 64, BATCH * HEADS), blk>>>(T, Wo, Weff);

    // 5) out_b = Qn_b @ Weff_b + bo
    dim3 gout(FEATS / 128, SEQ / 128, BATCH);
    gemm_tf32_kernel<<<gout, blk, SMEM_TOT>>>(Q, (size_t)SEQ * FEATS,
                                              Weff, (size_t)FEATS * FEATS,
                                              bo, out, (size_t)SEQ * FEATS,
                                              SEQ, FEATS, FEATS);
}

// round 11
// speedup vs baseline: 3.3523x; 1.9034x over previous
#include <cuda_runtime.h>
#include <cuda_fp16.h>
#include <math.h>
#include <stdint.h>

#define BATCH   4
#define SEQ     2048
#define FEATS   1024
#define HEADS   16
#define HDIM    64
#define MROWS   (BATCH*SEQ)   // 8192

// Scratch (device globals: allocation-free rule)
__device__ float g_Q[MROWS*FEATS];
__device__ float g_K[MROWS*FEATS];
__device__ float g_V[MROWS*FEATS];
__device__ float g_T[BATCH*HEADS*HDIM*HDIM];
__device__ float g_Weff[BATCH*FEATS*FEATS];

__device__ __forceinline__ uint32_t smem_u32(const void* p) {
    uint32_t a;
    asm("{ .reg .u64 t; cvta.to.shared.u64 t, %1; cvt.u32.u64 %0, t; }" : "=r"(a) : "l"(p));
    return a;
}
__device__ __forceinline__ uint32_t pack2h(float a, float b) {
    __half2 h = __floats2half2_rn(a, b);   // a -> lo, b -> hi
    return *(uint32_t*)&h;
}

// ---------------------------------------------------------------------------
// FP16 mma.sync m16n8k16 GEMM (fp32 accum) with ldmatrix fragment loads.
// C[z] = A[z] @ W[z] + bias. A row-major [M,K], W row-major [K,N].
// BM=BN=128, BK=32. 256 threads = 8 warps (2 wm x 4 wn), warp tile 64x32.
//
// Smem (static 32KB, double-buffered):
//  A stage (8KB): 128 rows x 64B (32 halfs, k-major). Row m at m*64; 16B chunk
//    c in 0..3 stored at c' = c ^ ((m>>1)&3)  -> ldmatrix.x4 phases conflict-free.
//  B stage (8KB): 32 k-rows x 256B (128 halfs, n-major). Row k at k*256; chunk
//    c in 0..15 stored at c' = c ^ (k&7)      -> ldmatrix.x4.trans conflict-free.
// ---------------------------------------------------------------------------
#define AB_STG 8192

__global__ __launch_bounds__(256, 2) void gemm_f16_kernel(
    const float* __restrict__ A, size_t strideA,
    const float* __restrict__ W, size_t strideW,
    const float* __restrict__ bias,
    float* __restrict__ C, size_t strideC,
    int M, int N, int K)
{
    __shared__ __align__(16) char smem[4 * AB_STG];
    const uint32_t sb = smem_u32(smem);

    A += (size_t)blockIdx.z * strideA;
    W += (size_t)blockIdx.z * strideW;
    C += (size_t)blockIdx.z * strideC;

    const int t    = threadIdx.x;
    const int lane = t & 31;
    const int warp = t >> 5;
    const int wm   = warp & 1;
    const int wn   = warp >> 1;
    const int bm   = blockIdx.y * 128;
    const int bn   = blockIdx.x * 128;
    const int qd   = lane >> 2;
    const int tg   = lane & 3;

    // A loader: j=0..3, u = t + j*256: row m = u>>3 (0..127), kq = u&7 (float4 idx)
    // B loader: r=0..3: k-row = warp*4 + r, n = lane*4 floats
    float acc[4][4][4];
#pragma unroll
    for (int mt = 0; mt < 4; mt++)
#pragma unroll
        for (int nt = 0; nt < 4; nt++)
#pragma unroll
            for (int r = 0; r < 4; r++) acc[mt][nt][r] = 0.0f;

    // Precomputed smem store offsets (stage-relative)
    uint32_t a_off[4], b_off[4];
#pragma unroll
    for (int j = 0; j < 4; j++) {
        int u = t + j * 256;
        int m = u >> 3, kq = u & 7;
        a_off[j] = (uint32_t)(m * 64 + (((kq >> 1) ^ ((m >> 1) & 3)) << 4) + (kq & 1) * 8);
    }
#pragma unroll
    for (int r = 0; r < 4; r++) {
        int k = warp * 4 + r;
        b_off[r] = (uint32_t)(k * 256 + (((lane >> 1) ^ (k & 7)) << 4) + (lane & 1) * 8);
    }

    // Prologue: stage 0 (k0 = 0)
    {
#pragma unroll
        for (int j = 0; j < 4; j++) {
            int u = t + j * 256;
            int m = u >> 3, kq = u & 7;
            float4 v = *(const float4*)&A[(size_t)(bm + m) * K + kq * 4];
            uint2 h; h.x = pack2h(v.x, v.y); h.y = pack2h(v.z, v.w);
            *(uint2*)(smem + a_off[j]) = h;
        }
#pragma unroll
        for (int r = 0; r < 4; r++) {
            int k = warp * 4 + r;
            float4 v = *(const float4*)&W[(size_t)k * N + bn + lane * 4];
            uint2 h; h.x = pack2h(v.x, v.y); h.y = pack2h(v.z, v.w);
            *(uint2*)(smem + 2 * AB_STG + b_off[r]) = h;
        }
    }
    __syncthreads();

    int s = 0;
    for (int k0 = 0; k0 < K; k0 += 32) {
        const bool has_next = (k0 + 32) < K;
        uint2 pa[4], pb[4];
        if (has_next) {
            const int kn = k0 + 32;
#pragma unroll
            for (int j = 0; j < 4; j++) {
                int u = t + j * 256;
                int m = u >> 3, kq = u & 7;
                float4 v = *(const float4*)&A[(size_t)(bm + m) * K + kn + kq * 4];
                pa[j].x = pack2h(v.x, v.y); pa[j].y = pack2h(v.z, v.w);
            }
#pragma unroll
            for (int r = 0; r < 4; r++) {
                int k = warp * 4 + r;
                float4 v = *(const float4*)&W[(size_t)(kn + k) * N + bn + lane * 4];
                pb[r].x = pack2h(v.x, v.y); pb[r].y = pack2h(v.z, v.w);
            }
        }

        const uint32_t ab = sb + s * AB_STG;
        const uint32_t bb = sb + 2 * AB_STG + s * AB_STG;

        // B fragments: ldmatrix.x4.trans per nt -> {b0s0, b1s0, b0s1, b1s1}
        uint32_t bf[4][4];
#pragma unroll
        for (int nt = 0; nt < 4; nt++) {
            uint32_t addr = bb + lane * 256 + ((((uint32_t)(wn * 4 + nt)) ^ (lane & 7)) << 4);
            asm volatile("ldmatrix.sync.aligned.m8n8.x4.trans.shared.b16 {%0,%1,%2,%3}, [%4];"
                         : "=r"(bf[nt][0]), "=r"(bf[nt][1]), "=r"(bf[nt][2]), "=r"(bf[nt][3])
                         : "r"(addr));
        }

#pragma unroll
        for (int ks2 = 0; ks2 < 2; ks2++) {
            uint32_t af[4][4];
#pragma unroll
            for (int mt = 0; mt < 4; mt++) {
                int ra = wm * 64 + mt * 16 + (lane & 15);
                int ca = 2 * ks2 + (lane >> 4);
                uint32_t addr = ab + ra * 64 + (((uint32_t)(ca ^ ((ra >> 1) & 3))) << 4);
                asm volatile("ldmatrix.sync.aligned.m8n8.x4.shared.b16 {%0,%1,%2,%3}, [%4];"
                             : "=r"(af[mt][0]), "=r"(af[mt][1]), "=r"(af[mt][2]), "=r"(af[mt][3])
                             : "r"(addr));
            }
#pragma unroll
            for (int mt = 0; mt < 4; mt++)
#pragma unroll
                for (int nt = 0; nt < 4; nt++) {
                    asm volatile(
                        "mma.sync.aligned.m16n8k16.row.col.f32.f16.f16.f32 "
                        "{%0,%1,%2,%3}, {%4,%5,%6,%7}, {%8,%9}, {%0,%1,%2,%3};\n"
                        : "+f"(acc[mt][nt][0]), "+f"(acc[mt][nt][1]),
                          "+f"(acc[mt][nt][2]), "+f"(acc[mt][nt][3])
                        : "r"(af[mt][0]), "r"(af[mt][1]),
                          "r"(af[mt][2]), "r"(af[mt][3]),
                          "r"(bf[nt][2 * ks2]), "r"(bf[nt][2 * ks2 + 1]));
                }
        }

        if (has_next) {
            char* na = smem + (s ^ 1) * AB_STG;
            char* nb = smem + 2 * AB_STG + (s ^ 1) * AB_STG;
#pragma unroll
            for (int j = 0; j < 4; j++) *(uint2*)(na + a_off[j]) = pa[j];
#pragma unroll
            for (int r = 0; r < 4; r++) *(uint2*)(nb + b_off[r]) = pb[r];
            __syncthreads();
            s ^= 1;
        }
    }

    // Epilogue: add bias, store. c0/c1 at (row, col*2), c2/c3 at (row+8, col*2).
#pragma unroll
    for (int mt = 0; mt < 4; mt++) {
        int r0 = bm + wm * 64 + mt * 16 + qd;
#pragma unroll
        for (int nt = 0; nt < 4; nt++) {
            int cb = bn + wn * 32 + nt * 8 + tg * 2;
            float b0 = bias[cb], b1 = bias[cb + 1];
            float2 o0, o1;
            o0.x = acc[mt][nt][0] + b0; o0.y = acc[mt][nt][1] + b1;
            o1.x = acc[mt][nt][2] + b0; o1.y = acc[mt][nt][3] + b1;
            *(float2*)&C[(size_t)r0 * N + cb]       = o0;
            *(float2*)&C[(size_t)(r0 + 8) * N + cb] = o1;
        }
    }
}

// ---------------------------------------------------------------------------
// L2-normalize each 64-elem head chunk of Q and K in place (F.normalize, eps=1e-12)
// ---------------------------------------------------------------------------
__global__ __launch_bounds__(256) void l2norm_kernel(float* __restrict__ Q,
                                                     float* __restrict__ K)
{
    const int ngroups = MROWS * HEADS;
    int wid  = (blockIdx.x * blockDim.x + threadIdx.x) >> 5;
    int lane = threadIdx.x & 31;
    if (wid >= 2 * ngroups) return;
    float* base = (wid < ngroups) ? Q : K;
    int g = (wid < ngroups) ? wid : wid - ngroups;
    float* p = base + (size_t)g * HDIM;

    float2 v = *(float2*)(p + lane * 2);
    float ss = v.x * v.x + v.y * v.y;
#pragma unroll
    for (int o = 16; o > 0; o >>= 1) ss += __shfl_xor_sync(0xFFFFFFFFu, ss, o);
    float nrm = sqrtf(ss);
    float inv = 1.0f / fmaxf(nrm, 1e-12f);
    v.x *= inv; v.y *= inv;
    *(float2*)(p + lane * 2) = v;
}

// ---------------------------------------------------------------------------
// T[b,h] = (K_{b,h}^T @ V_{b,h}) * SEQ^{-sigmoid(m[h])}
// ---------------------------------------------------------------------------
__global__ __launch_bounds__(256) void ktv_kernel(const float* __restrict__ Kb,
                                                  const float* __restrict__ Vb,
                                                  const float* __restrict__ m,
                                                  float* __restrict__ T)
{
    int bh = blockIdx.x;
    int b = bh >> 4, h = bh & 15;
    __shared__ float Ks[32][64];
    __shared__ float Vs[32][64];
    const int tid = threadIdx.x;
    const int tx = tid & 15, ty = tid >> 4;
    const int lr = tid >> 4;
    const int lc = (tid & 15) * 4;

    const float* Kp = Kb + (size_t)b * SEQ * FEATS + h * HDIM;
    const float* Vp = Vb + (size_t)b * SEQ * FEATS + h * HDIM;

    float acc[4][4];
#pragma unroll
    for (int i = 0; i < 4; i++)
#pragma unroll
        for (int j = 0; j < 4; j++) acc[i][j] = 0.0f;

    for (int j0 = 0; j0 < SEQ; j0 += 32) {
#pragma unroll
        for (int i = 0; i < 2; i++) {
            int r = lr + i * 16;
            *(float4*)&Ks[r][lc] = *(const float4*)&Kp[(size_t)(j0 + r) * FEATS + lc];
            *(float4*)&Vs[r][lc] = *(const float4*)&Vp[(size_t)(j0 + r) * FEATS + lc];
        }
        __syncthreads();
#pragma unroll
        for (int j = 0; j < 32; j++) {
            float ra[4], rb[4];
            *(float4*)ra = *(const float4*)&Ks[j][ty * 4];
            *(float4*)rb = *(const float4*)&Vs[j][tx * 4];
#pragma unroll
            for (int i = 0; i < 4; i++)
#pragma unroll
                for (int c = 0; c < 4; c++)
                    acc[i][c] += ra[i] * rb[c];
        }
        __syncthreads();
    }

    float sig = 1.0f / (1.0f + expf(-m[h]));
    float invscale = powf((float)SEQ, -sig);

#pragma unroll
    for (int i = 0; i < 4; i++) {
        int e = ty * 4 + i;
        float4 o;
        o.x = acc[i][0] * invscale;
        o.y = acc[i][1] * invscale;
        o.z = acc[i][2] * invscale;
        o.w = acc[i][3] * invscale;
        *(float4*)&T[(size_t)bh * 4096 + e * 64 + tx * 4] = o;
    }
}

// ---------------------------------------------------------------------------
// Weff[b][h*64+e][n] = sum_d T[b,h][e][d] * Wo[h*64+d][n]
// ---------------------------------------------------------------------------
__global__ __launch_bounds__(256) void weff_kernel(const float* __restrict__ T,
                                                   const float* __restrict__ Wo,
                                                   float* __restrict__ Weff)
{
    int bh = blockIdx.y;
    int b = bh >> 4, h = bh & 15;
    int n0 = blockIdx.x * 64;
    __shared__ float Tst[64][64];
    __shared__ float Ws[64][64];
    const int tid = threadIdx.x;
    const int lr = tid >> 4;
    const int lc = (tid & 15) * 4;

#pragma unroll
    for (int i = 0; i < 4; i++) {
        int r = lr + i * 16;
        float4 v = *(const float4*)&T[(size_t)bh * 4096 + r * 64 + lc];
        Tst[lc + 0][r] = v.x;
        Tst[lc + 1][r] = v.y;
        Tst[lc + 2][r] = v.z;
        Tst[lc + 3][r] = v.w;
        *(float4*)&Ws[r][lc] = *(const float4*)&Wo[(size_t)(h * HDIM + r) * FEATS + n0 + lc];
    }
    __syncthreads();

    const int tx = tid & 15, ty = tid >> 4;
    float acc[4][4];
#pragma unroll
    for (int i = 0; i < 4; i++)
#pragma unroll
        for (int j = 0; j < 4; j++) acc[i][j] = 0.0f;

#pragma unroll
    for (int d = 0; d < 64; d++) {
        float ra[4], rb[4];
        *(float4*)ra = *(const float4*)&Tst[d][ty * 4];
        *(float4*)rb = *(const float4*)&Ws[d][tx * 4];
#pragma unroll
        for (int i = 0; i < 4; i++)
#pragma unroll
            for (int j = 0; j < 4; j++)
                acc[i][j] += ra[i] * rb[j];
    }

#pragma unroll
    for (int i = 0; i < 4; i++) {
        int e = ty * 4 + i;
        float4 o;
        o.x = acc[i][0]; o.y = acc[i][1]; o.z = acc[i][2]; o.w = acc[i][3];
        *(float4*)&Weff[((size_t)b * FEATS + h * HDIM + e) * FEATS + n0 + tx * 4] = o;
    }
}

// ---------------------------------------------------------------------------
// kernel_launch
// ---------------------------------------------------------------------------
extern "C" void kernel_launch(void* const* d_in, const int* in_sizes, int n_in,
                              void* d_out, int out_size)
{
    (void)in_sizes; (void)n_in; (void)out_size;
    const float* x  = (const float*)d_in[0];
    const float* Wq = (const float*)d_in[1];
    const float* bq = (const float*)d_in[2];
    const float* Wk = (const float*)d_in[3];
    const float* bk = (const float*)d_in[4];
    const float* Wv = (const float*)d_in[5];
    const float* bv = (const float*)d_in[6];
    const float* Wo = (const float*)d_in[7];
    const float* bo = (const float*)d_in[8];
    const float* m  = (const float*)d_in[9];
    float* out = (float*)d_out;

    float *Q, *K, *V, *T, *Weff;
    cudaGetSymbolAddress((void**)&Q,    g_Q);
    cudaGetSymbolAddress((void**)&K,    g_K);
    cudaGetSymbolAddress((void**)&V,    g_V);
    cudaGetSymbolAddress((void**)&T,    g_T);
    cudaGetSymbolAddress((void**)&Weff, g_Weff);

    dim3 blk(256);

    // 1) Q/K/V projections: fp16 m16n8k16 tensor cores (fp32 accum)
    dim3 gqkv(FEATS / 128, MROWS / 128, 1);
    gemm_f16_kernel<<<gqkv, blk>>>(x, 0, Wq, 0, bq, Q, 0, MROWS, FEATS, FEATS);
    gemm_f16_kernel<<<gqkv, blk>>>(x, 0, Wk, 0, bk, K, 0, MROWS, FEATS, FEATS);
    gemm_f16_kernel<<<gqkv, blk>>>(x, 0, Wv, 0, bv, V, 0, MROWS, FEATS, FEATS);

    // 2) L2-normalize Q and K per head chunk (in place).
    {
        int total_warps = 2 * MROWS * HEADS;          // 262144
        int nblocks = total_warps / 8;                // 32768
        l2norm_kernel<<<nblocks, 256>>>(Q, K);
    }

    // 3) T = (K^T V)/scale per (b,h)
    ktv_kernel<<<BATCH * HEADS, blk>>>(K, V, m, T);

    // 4) Weff_b = blockrows(T_bh @ Wo_h)
    weff_kernel<<<dim3(FEATS / 64, BATCH * HEADS), blk>>>(T, Wo, Weff);

    // 5) out_b = Qn_b @ Weff_b + bo
    dim3 gout(FEATS / 128, SEQ / 128, BATCH);
    gemm_f16_kernel<<<gout, blk>>>(Q, (size_t)SEQ * FEATS,
                                   Weff, (size_t)FEATS * FEATS,
                                   bo, out, (size_t)SEQ * FEATS,
                                   SEQ, FEATS, FEATS);
}